// round 5
// baseline (speedup 1.0000x reference)
#include <cuda_runtime.h>
#include <cstdint>

// Symmetric one-pass Chamfer. d(i,j) computed once; row mins (gt->gen) and
// col mins (gen->gt) extracted simultaneously.
// Block tile: 64 rows (gt) x 256 cols (gen), 256 threads.
//   thread = 8 rows (4 f32x2 packed pairs, regs) x 8 cols (splatted, smem).
//   warp lane (tc) = col group -> row-min block reduce is pure warp shuffle.
// Grid: 64 col-blocks x 256 row-blocks = 16384 blocks.

#define N_PTS   16384
#define NB_COL  64          // 16384 / 256
#define NB_ROW  256         // 16384 / 64
#define TPB     256

#define RED_BLOCKS 32       // 16 col-reduce + 16 row-reduce

typedef unsigned long long u64;

// Every slot written every run -> no init kernel needed.
__device__ float g_rowpart[NB_COL][N_PTS];   // [col-block][row] : 4 MB
__device__ float g_colpart[NB_ROW][N_PTS];   // [row-block][col] : 16 MB
__device__ float g_partial[RED_BLOCKS];
__device__ unsigned int g_ctr;               // self-resetting (wraps to 0)

// ---------------- f32x2 helpers ----------------
__device__ __forceinline__ u64 pack2(float a, float b) {
    u64 r;
    asm("mov.b64 %0, {%1, %2};" : "=l"(r) : "f"(a), "f"(b));
    return r;
}
__device__ __forceinline__ u64 fma2(u64 a, u64 b, u64 c) {
    u64 d;
    asm("fma.rn.f32x2 %0, %1, %2, %3;" : "=l"(d) : "l"(a), "l"(b), "l"(c));
    return d;
}
__device__ __forceinline__ u64 add2(u64 a, u64 b) {
    u64 d;
    asm("add.rn.f32x2 %0, %1, %2;" : "=l"(d) : "l"(a), "l"(b));
    return d;
}
__device__ __forceinline__ void unpack2(u64 v, float& lo, float& hi) {
    asm("mov.b64 {%0, %1}, %2;" : "=f"(lo), "=f"(hi) : "l"(v));
}

// ---------------- Kernel 1: main symmetric pairwise min ----------------
__global__ __launch_bounds__(TPB, 3) void chamfer_sym_kernel(
    const float* __restrict__ gt, const float* __restrict__ gen) {

    __shared__ u64 sCX[256], sCY[256], sCZ[256], sCB[256];  // splatted cols: 8 KB
    __shared__ float sRraw[192];                            // 64 row points x 3
    __shared__ float scol[256][9];                          // padded, conflict-free

    const int tid = threadIdx.x;
    const int tc  = tid & 31;    // lane  = col group (0..31)
    const int tr  = tid >> 5;    // warp  = row group (0..7)
    const int bx  = blockIdx.x;  // col block (gen)
    const int by  = blockIdx.y;  // row block (gt)

    // ---- stage 64 raw rows (gt) ----
    if (tid < 192) sRraw[tid] = gt[by * 192 + tid];

    // ---- stage 256 cols (gen): one col per thread; splat -2*coord, |b|^2 ----
    {
        int g = (bx * 256 + tid) * 3;
        float x = gen[g + 0];
        float y = gen[g + 1];
        float z = gen[g + 2];
        float cb = x * x + y * y + z * z;
        sCX[tid] = pack2(-2.0f * x, -2.0f * x);
        sCY[tid] = pack2(-2.0f * y, -2.0f * y);
        sCZ[tid] = pack2(-2.0f * z, -2.0f * z);
        sCB[tid] = pack2(cb, cb);
    }
    __syncthreads();

    // ---- this thread's 8 rows as 4 packed pairs (warp-broadcast reads) ----
    u64 rx2[4], ry2[4], rz2[4], rca2[4];
#pragma unroll
    for (int p = 0; p < 4; p++) {
        int r0 = tr * 8 + 2 * p;
        float x0 = sRraw[r0 * 3 + 0], y0 = sRraw[r0 * 3 + 1], z0 = sRraw[r0 * 3 + 2];
        float x1 = sRraw[r0 * 3 + 3], y1 = sRraw[r0 * 3 + 4], z1 = sRraw[r0 * 3 + 5];
        rx2[p]  = pack2(x0, x1);
        ry2[p]  = pack2(y0, y1);
        rz2[p]  = pack2(z0, z1);
        rca2[p] = pack2(x0 * x0 + y0 * y0 + z0 * z0,
                        x1 * x1 + y1 * y1 + z1 * z1);
    }

    float rowm[8], colm[8];
#pragma unroll
    for (int k = 0; k < 8; k++) { rowm[k] = 3.4e38f; colm[k] = 3.4e38f; }

    // ---- main loop: 8 cols x 4 packed row-pairs = 64 pairs/thread ----
#pragma unroll
    for (int c = 0; c < 8; c++) {
        const int ci = tc + 32 * c;
        u64 cx2 = sCX[ci];
        u64 cy2 = sCY[ci];
        u64 cz2 = sCZ[ci];
        u64 cb2 = sCB[ci];
#pragma unroll
        for (int p = 0; p < 4; p++) {
            u64 acc = add2(cb2, rca2[p]);          // seed = ca + cb (both lanes)
            acc = fma2(rz2[p], cz2, acc);
            acc = fma2(ry2[p], cy2, acc);
            acc = fma2(rx2[p], cx2, acc);          // acc = full d, 2 rows
            float lo, hi;
            unpack2(acc, lo, hi);
            rowm[2 * p]     = fminf(rowm[2 * p], lo);
            rowm[2 * p + 1] = fminf(rowm[2 * p + 1], hi);
            colm[c] = fminf(colm[c], fminf(lo, hi));
        }
    }

    // ---- row mins: reduce over tc = pure intra-warp shuffle ----
#pragma unroll
    for (int k = 0; k < 8; k++) {
#pragma unroll
        for (int off = 16; off > 0; off >>= 1)
            rowm[k] = fminf(rowm[k], __shfl_xor_sync(0xFFFFFFFFu, rowm[k], off));
    }
    if (tc == 0) {
#pragma unroll
        for (int k = 0; k < 8; k++)
            g_rowpart[bx][by * 64 + tr * 8 + k] = rowm[k];
    }

    // ---- col mins: reduce over tr (cross-warp) via padded smem ----
#pragma unroll
    for (int c = 0; c < 8; c++) scol[tc + 32 * c][tr] = colm[c];
    __syncthreads();
    {
        float m = scol[tid][0];
#pragma unroll
        for (int i = 1; i < 8; i++) m = fminf(m, scol[tid][i]);
        g_colpart[by][bx * 256 + tid] = m;
    }
}

// ---------------- Kernel 2: global reduce + fused final scalar ----------------
// Blocks 0..15 : col reduce (one col/thread, min over 256 partials)
// Blocks 16..31: row reduce (one row/thread, min over 64 partials)
// Last block to finish sums the 32 block-partials (fixed order, deterministic).
__global__ __launch_bounds__(1024) void reduce_sym_kernel(float* __restrict__ out) {
    const int tid = threadIdx.x;
    const int bx  = blockIdx.x;
    float v;

    if (bx < 16) {
        int j = bx * 1024 + tid;                 // col 0..16383
        float m = 3.4e38f;
#pragma unroll 8
        for (int p = 0; p < NB_ROW; p++)
            m = fminf(m, g_colpart[p][j]);
        v = m;
    } else {
        int r = (bx - 16) * 1024 + tid;          // row 0..16383
        float m = 3.4e38f;
#pragma unroll 8
        for (int p = 0; p < NB_COL; p++)
            m = fminf(m, g_rowpart[p][r]);
        v = m;
    }

    // block sum
    __shared__ float ssum[32];
    __shared__ int s_last;
#pragma unroll
    for (int off = 16; off > 0; off >>= 1)
        v += __shfl_xor_sync(0xFFFFFFFFu, v, off);
    int lane = tid & 31;
    int wid  = tid >> 5;
    if (lane == 0) ssum[wid] = v;
    __syncthreads();
    if (tid < 32) {
        float w = ssum[tid];
#pragma unroll
        for (int off = 16; off > 0; off >>= 1)
            w += __shfl_xor_sync(0xFFFFFFFFu, w, off);
        if (tid == 0) {
            g_partial[bx] = w;
            __threadfence();
            unsigned int old = atomicInc(&g_ctr, RED_BLOCKS - 1);  // wraps -> self-reset
            s_last = (old == RED_BLOCKS - 1);
        }
    }
    __syncthreads();

    if (s_last && tid < 32) {
        volatile float* gp = g_partial;
        float w = gp[tid];
#pragma unroll
        for (int off = 16; off > 0; off >>= 1)
            w += __shfl_xor_sync(0xFFFFFFFFu, w, off);
        if (tid == 0)
            out[0] = w * (1.0f / (float)N_PTS);
    }
}

// ---------------- launch ----------------
extern "C" void kernel_launch(void* const* d_in, const int* in_sizes, int n_in,
                              void* d_out, int out_size) {
    const float* gt  = (const float*)d_in[0];
    const float* gen = (const float*)d_in[1];
    float* out = (float*)d_out;

    dim3 grid(NB_COL, NB_ROW);
    chamfer_sym_kernel<<<grid, TPB>>>(gt, gen);
    reduce_sym_kernel<<<RED_BLOCKS, 1024>>>(out);
}